// round 11
// baseline (speedup 1.0000x reference)
#include <cuda_runtime.h>
#include <cuda_fp16.h>
#include <math.h>
#include <stdint.h>

#define NN 1024
#define BT 256  // threads for butterfly kernel

// ---------------- scratch (__device__ globals; no runtime alloc) ----------------
__device__ float   g_W[NN * NN];            // 4 MB : M[k][n] (row k = butterfly(e_k))
__device__ __half  g_WhT[NN * NN];          // 2 MB : fp16(W), transposed [n][k]
__device__ __half  g_xh[16384 * NN];        // 32 MB : fp16(x)
__device__ __half  g_xl[16384 * NN];        // 32 MB : fp16(x - xh)

// ---------------- PTX helpers (all family-agnostic: sm_80+ features) ----------------
__device__ __forceinline__ uint32_t smem_u32(const void* p) {
    uint32_t a;
    asm("{ .reg .u64 t; cvta.to.shared.u64 t, %1; cvt.u32.u64 %0, t; }" : "=r"(a) : "l"(p));
    return a;
}
#define CP_ASYNC16(s, g) \
    asm volatile("cp.async.cg.shared.global [%0], [%1], 16;" :: "r"(s), "l"(g))
#define CP_COMMIT() asm volatile("cp.async.commit_group;" ::: "memory")
#define CP_WAIT2()  asm volatile("cp.async.wait_group 2;" ::: "memory")
#define CP_WAIT1()  asm volatile("cp.async.wait_group 1;" ::: "memory")
#define CP_WAIT0()  asm volatile("cp.async.wait_group 0;" ::: "memory")
#define LDSM4(r, addr) \
    asm volatile("ldmatrix.sync.aligned.m8n8.x4.shared.b16 {%0,%1,%2,%3}, [%4];" \
        : "=r"((r)[0]), "=r"((r)[1]), "=r"((r)[2]), "=r"((r)[3]) : "r"(addr))
#define MMA16816(d, a, b) \
    asm volatile("mma.sync.aligned.m16n8k16.row.col.f32.f16.f16.f32 " \
        "{%0,%1,%2,%3}, {%4,%5,%6,%7}, {%8,%9}, {%0,%1,%2,%3};" \
        : "+f"((d)[0]), "+f"((d)[1]), "+f"((d)[2]), "+f"((d)[3]) \
        : "r"((a)[0]), "r"((a)[1]), "r"((a)[2]), "r"((a)[3]), "r"((b)[0]), "r"((b)[1]))

// ================= butterfly on identity rows -> g_W =================
__global__ __launch_bounds__(BT) void butterfly_ident_kernel(
    const float* __restrict__ perm_logit, const float* __restrict__ abcd, int depth)
{
    __shared__ float2 buf[2][NN];
    const int row = blockIdx.x;
    const int t = threadIdx.x;
    #pragma unroll
    for (int u = 0; u < NN / BT; ++u) {
        int i = t + u * BT;
        buf[0][i] = make_float2(i == row ? 1.0f : 0.0f, 0.0f);
    }
    int cur = 0;
    __syncthreads();

    for (int d = 0; d < depth; ++d) {
        const float p0 = 1.0f / (1.0f + expf(-perm_logit[d * 3 + 0]));
        const float p1 = 1.0f / (1.0f + expf(-perm_logit[d * 3 + 1]));
        const float p2 = 1.0f / (1.0f + expf(-perm_logit[d * 3 + 2]));
        for (int m = 4; m <= NN; m <<= 1) {
            const int half = m >> 1;
            const int nxt = cur ^ 1;
            #pragma unroll
            for (int u = 0; u < NN / BT; ++u) {
                int i = t + u * BT;
                int blk = i & ~(m - 1);
                int j = i - blk;
                bool second = (j >= half);
                float pr = second ? p2 : p1;
                int sj  = second ? (2 * (j - half) + 1) : (2 * j);
                int rj  = second ? (m + half - 1 - j)   : (half - 1 - j);
                int srj = second ? (2 * (rj - half) + 1) : (2 * rj);
                float2 a  = buf[cur][blk + j];
                float2 bb = buf[cur][blk + sj];
                float2 c  = buf[cur][blk + rj];
                float2 dd = buf[cur][blk + srj];
                float ex = a.x + p0 * (bb.x - a.x);
                float ey = a.y + p0 * (bb.y - a.y);
                float fx = c.x + p0 * (dd.x - c.x);
                float fy = c.y + p0 * (dd.y - c.y);
                buf[nxt][i] = make_float2(ex + pr * (fx - ex), ey + pr * (fy - ey));
            }
            __syncthreads();
            cur = nxt;
        }
        const float2* abd = (const float2*)(abcd) + (size_t)d * (4 * NN - 4);
        int lh = 0;
        for (int m = 2; m <= NN; m <<= 1, ++lh) {
            const int half = m >> 1;
            const float2* W = abd + (4 * NN - 4 * m);
            const int nxt = cur ^ 1;
            #pragma unroll
            for (int u = 0; u < (NN / 2) / BT; ++u) {
                int p  = t + u * BT;
                int bi = p >> lh;
                int k  = p & (half - 1);
                int i0 = bi * m + k;
                int i1 = i0 + half;
                float2 x0 = buf[cur][i0];
                float2 x1 = buf[cur][i1];
                float2 A  = W[k];
                float2 Bw = W[half + k];
                float2 C  = W[2 * half + k];
                float2 D  = W[3 * half + k];
                float2 y0, y1;
                y0.x = A.x * x0.x - A.y * x0.y + Bw.x * x1.x - Bw.y * x1.y;
                y0.y = A.x * x0.y + A.y * x0.x + Bw.x * x1.y + Bw.y * x1.x;
                y1.x = C.x * x0.x - C.y * x0.y + D.x * x1.x - D.y * x1.y;
                y1.y = C.x * x0.y + C.y * x0.x + D.x * x1.y + D.y * x1.x;
                buf[nxt][i0] = y0;
                buf[nxt][i1] = y1;
            }
            __syncthreads();
            cur = nxt;
        }
    }
    #pragma unroll
    for (int u = 0; u < NN / BT; ++u) {
        int i = t + u * BT;
        g_W[(size_t)row * NN + i] = buf[cur][i].x;
    }
}

// ================= convert W -> transposed fp16 =================
__global__ void convW_kernel()
{
    __shared__ float tile[32][33];
    int tx = threadIdx.x, ty = threadIdx.y;
    int bx = blockIdx.x, by = blockIdx.y;
    #pragma unroll
    for (int k = 0; k < 4; ++k) {
        int krow = by * 32 + ty + 8 * k;
        tile[ty + 8 * k][tx] = g_W[(size_t)krow * NN + bx * 32 + tx];
    }
    __syncthreads();
    #pragma unroll
    for (int k = 0; k < 4; ++k) {
        int n  = bx * 32 + ty + 8 * k;
        int kk = by * 32 + tx;
        g_WhT[(size_t)n * NN + kk] = __float2half(tile[tx][ty + 8 * k]);
    }
}

// ================= convert x -> fp16 split (xh + xl ~ 22-bit x) =================
__global__ void convX_kernel(const float* __restrict__ x, int n4)
{
    int i = blockIdx.x * blockDim.x + threadIdx.x;
    if (i >= n4) return;
    float4 v = ((const float4*)x)[i];
    __half h0 = __float2half(v.x);
    __half h1 = __float2half(v.y);
    __half h2 = __float2half(v.z);
    __half h3 = __float2half(v.w);
    __half2* dh = (__half2*)g_xh + i * 2;
    __half2* dl = (__half2*)g_xl + i * 2;
    dh[0] = __half2(h0, h1);
    dh[1] = __half2(h2, h3);
    dl[0] = __half2(__float2half(v.x - __half2float(h0)),
                    __float2half(v.y - __half2float(h1)));
    dl[1] = __half2(__float2half(v.z - __half2float(h2)),
                    __float2half(v.w - __half2float(h3)));
}

// ================= HMMA GEMM: out = xh*Wh + xl*Wh + bias =================
// CTA tile 128x256, warp tile 64x64 (8 warps = 2 M x 4 N). K-stage 32.
// 4-slot cp.async ring, 3 stages in flight, one __syncthreads per stage.
// Smem rows padded to 40 halves (80B) -> conflict-free ldmatrix.
#define TM 128
#define TN 256
#define TK 32
#define PAD 40
#define AST (TM * PAD)                  // 5120 halves
#define BST (TN * PAD)                  // 10240 halves
#define NRING 4
#define ABYTES (AST * 2)                // 10240 B
#define BBYTES (BST * 2)                // 20480 B
#define SMEM_GEMM (NRING * (ABYTES + BBYTES))   // 122880 B
#define CHUNKS_PER_PASS (NN / TK)       // 32
#define NPASSES 2
#define NSTAGES_TOT (NPASSES * CHUNKS_PER_PASS)  // 64

__global__ __launch_bounds__(256) void gemm_kernel(
    const float* __restrict__ bias, float* __restrict__ out)
{
    extern __shared__ __half smem[];
    __half* As = smem;                       // NRING stages of A
    __half* Bs = smem + NRING * AST;         // NRING stages of B

    const int tid = threadIdx.x;
    const int lane = tid & 31;
    const int wid = tid >> 5;
    const int wm = wid & 1;       // 2 warps over M (64 rows each)
    const int wn = wid >> 1;      // 4 warps over N (64 cols each)
    const int gn = blockIdx.x;    // N block (4 blocks)
    const int gm = blockIdx.y;    // M block (128 blocks)

    float acc[4][8][4];
    #pragma unroll
    for (int mf = 0; mf < 4; ++mf)
        #pragma unroll
        for (int nf = 0; nf < 8; ++nf)
            #pragma unroll
            for (int q = 0; q < 4; ++q) acc[mf][nf][q] = 0.0f;

    const uint32_t sAbase = smem_u32(As);
    const uint32_t sBbase = smem_u32(Bs);

    // cp.async mapping: A = 512 chunks (2/thread), B = 1024 chunks (4/thread).
    const int r0  = tid >> 2;           // row 0..63
    const int cc0 = tid & 3;            // 16B chunk within row
    const uint32_t w0 = (uint32_t)(r0 * 80 + cc0 * 16);
    const uint32_t w1 = w0 + 64 * 80;
    const uint32_t w2 = w0 + 128 * 80;
    const uint32_t w3 = w0 + 192 * 80;

    const __half* const Aps[NPASSES] = { g_xh, g_xl };

    auto issue = [&](int s, int slot) {
        const int pass = s >> 5;                       // 32 chunks per pass
        const int k0 = (s & (CHUNKS_PER_PASS - 1)) * TK;
        const __half* Ap = Aps[pass] + (size_t)(gm * TM) * NN + k0;
        const __half* Bp = g_WhT + (size_t)(gn * TN) * NN + k0;
        const uint32_t sa = sAbase + (uint32_t)(slot * ABYTES);
        const uint32_t sb = sBbase + (uint32_t)(slot * BBYTES);
        CP_ASYNC16(sa + w0, Ap + (size_t)r0 * NN + cc0 * 8);
        CP_ASYNC16(sa + w1, Ap + (size_t)(r0 + 64) * NN + cc0 * 8);
        CP_ASYNC16(sb + w0, Bp + (size_t)r0 * NN + cc0 * 8);
        CP_ASYNC16(sb + w1, Bp + (size_t)(r0 + 64) * NN + cc0 * 8);
        CP_ASYNC16(sb + w2, Bp + (size_t)(r0 + 128) * NN + cc0 * 8);
        CP_ASYNC16(sb + w3, Bp + (size_t)(r0 + 192) * NN + cc0 * 8);
        CP_COMMIT();
    };

    // ldmatrix lane address components
    const int a_r = (lane & 7) | (((lane >> 3) & 1) << 3);   // row 0..15 within frag
    const int a_c = ((lane >> 4) & 1) * 8;                   // +8 elems for mats 2,3
    const int b_n = (lane & 7) | (((lane >> 4) & 1) << 3);   // n row within 16
    const int b_k = ((lane >> 3) & 1) * 8;                   // +8 elems for mats 1,3
    const uint32_t aoff = (uint32_t)((wm * 64 + a_r) * 80 + a_c * 2);
    const uint32_t boff = (uint32_t)((wn * 64 + b_n) * 80 + b_k * 2);

    // prologue: 3 stages in flight
    issue(0, 0);
    issue(1, 1);
    issue(2, 2);

    int slot = 0, islot = 3;   // compute slot; next issue slot
    for (int s = 0; s < NSTAGES_TOT; ++s) {
        if      (s + 1 >= NSTAGES_TOT) { CP_WAIT0(); }
        else if (s + 2 >= NSTAGES_TOT) { CP_WAIT1(); }
        else                           { CP_WAIT2(); }
        __syncthreads();   // stage s visible; all warps done with previous use of slot
        if (s + 3 < NSTAGES_TOT) {
            issue(s + 3, islot);
            if (++islot == NRING) islot = 0;
        }
        const uint32_t sa = sAbase + (uint32_t)(slot * ABYTES) + aoff;
        const uint32_t sb = sBbase + (uint32_t)(slot * BBYTES) + boff;
        if (++slot == NRING) slot = 0;
        #pragma unroll
        for (int kk = 0; kk < 2; ++kk) {
            uint32_t af[4][4];
            #pragma unroll
            for (int g2 = 0; g2 < 4; ++g2)
                LDSM4(af[g2], sa + kk * 32 + g2 * 16 * 80);
            uint32_t bfr[4][4];
            #pragma unroll
            for (int g2 = 0; g2 < 4; ++g2)
                LDSM4(bfr[g2], sb + kk * 32 + g2 * 16 * 80);
            #pragma unroll
            for (int mf = 0; mf < 4; ++mf)
                #pragma unroll
                for (int nf = 0; nf < 8; ++nf) {
                    uint32_t bb[2] = { bfr[nf >> 1][(nf & 1) * 2],
                                       bfr[nf >> 1][(nf & 1) * 2 + 1] };
                    MMA16816(acc[mf][nf], af[mf], bb);
                }
        }
    }

    // epilogue: add bias, store fp32
    const int row0 = gm * TM + wm * 64 + (lane >> 2);
    const int col0 = gn * TN + wn * 64 + (lane & 3) * 2;
    #pragma unroll
    for (int mf = 0; mf < 4; ++mf) {
        #pragma unroll
        for (int nf = 0; nf < 8; ++nf) {
            const int r = row0 + mf * 16;
            const int c = col0 + nf * 8;
            const float b0 = __ldg(bias + c);
            const float b1 = __ldg(bias + c + 1);
            float2 v0 = make_float2(acc[mf][nf][0] + b0, acc[mf][nf][1] + b1);
            float2 v1 = make_float2(acc[mf][nf][2] + b0, acc[mf][nf][3] + b1);
            *(float2*)(out + (size_t)r * NN + c) = v0;
            *(float2*)(out + (size_t)(r + 8) * NN + c) = v1;
        }
    }
}

// ================= launch =================
extern "C" void kernel_launch(void* const* d_in, const int* in_sizes, int n_in,
                              void* d_out, int out_size)
{
    const float* x          = (const float*)d_in[0];  // (B, 1024)
    const float* perm_logit = (const float*)d_in[1];  // (DEPTH, 3)
    const float* abcd       = (const float*)d_in[2];  // (DEPTH, 4092, 2)
    const float* bias       = (const float*)d_in[3];  // (1024,)
    float* out = (float*)d_out;

    int Bn = in_sizes[0] / NN;
    int depth = in_sizes[1] / 3;

    static bool attr_set = false;
    if (!attr_set) {
        cudaFuncSetAttribute(gemm_kernel, cudaFuncAttributeMaxDynamicSharedMemorySize, SMEM_GEMM);
        attr_set = true;
    }

    // 1) M from butterfly on identity
    butterfly_ident_kernel<<<NN, BT>>>(perm_logit, abcd, depth);
    // 2) W -> transposed fp16
    convW_kernel<<<dim3(32, 32), dim3(32, 8)>>>();
    // 3) x -> fp16 split (xh + xl)
    int n4 = Bn * NN / 4;
    convX_kernel<<<(n4 + 255) / 256, 256>>>(x, n4);
    // 4) HMMA GEMM, 2-pass accumulation, CTA 128x256, warp 64x64
    gemm_kernel<<<dim3(NN / TN, Bn / TM), 256, SMEM_GEMM>>>(bias, out);
}

// round 12
// speedup vs baseline: 1.8084x; 1.8084x over previous
#include <cuda_runtime.h>
#include <cuda_fp16.h>
#include <math.h>
#include <stdint.h>

#define NN 1024
#define BT 256  // threads for butterfly kernel

// ---------------- scratch (__device__ globals; no runtime alloc) ----------------
__device__ float   g_W[NN * NN];            // 4 MB : M[k][n] (row k = butterfly(e_k))
__device__ __half  g_WhT[NN * NN];          // 2 MB : fp16(W), transposed [n][k]
__device__ __half  g_xh[16384 * NN];        // 32 MB : fp16(x)

// ---------------- PTX helpers (all family-agnostic: sm_80+ features) ----------------
__device__ __forceinline__ uint32_t smem_u32(const void* p) {
    uint32_t a;
    asm("{ .reg .u64 t; cvta.to.shared.u64 t, %1; cvt.u32.u64 %0, t; }" : "=r"(a) : "l"(p));
    return a;
}
#define CP_ASYNC16(s, g) \
    asm volatile("cp.async.cg.shared.global [%0], [%1], 16;" :: "r"(s), "l"(g))
#define CP_COMMIT() asm volatile("cp.async.commit_group;" ::: "memory")
#define CP_WAIT1()  asm volatile("cp.async.wait_group 1;" ::: "memory")
#define CP_WAIT0()  asm volatile("cp.async.wait_group 0;" ::: "memory")
#define LDSM4(r, addr) \
    asm volatile("ldmatrix.sync.aligned.m8n8.x4.shared.b16 {%0,%1,%2,%3}, [%4];" \
        : "=r"((r)[0]), "=r"((r)[1]), "=r"((r)[2]), "=r"((r)[3]) : "r"(addr))
#define MMA16816(d, a, b) \
    asm volatile("mma.sync.aligned.m16n8k16.row.col.f32.f16.f16.f32 " \
        "{%0,%1,%2,%3}, {%4,%5,%6,%7}, {%8,%9}, {%0,%1,%2,%3};" \
        : "+f"((d)[0]), "+f"((d)[1]), "+f"((d)[2]), "+f"((d)[3]) \
        : "r"((a)[0]), "r"((a)[1]), "r"((a)[2]), "r"((a)[3]), "r"((b)[0]), "r"((b)[1]))

// ================= butterfly on identity rows -> g_W =================
__global__ __launch_bounds__(BT) void butterfly_ident_kernel(
    const float* __restrict__ perm_logit, const float* __restrict__ abcd, int depth)
{
    __shared__ float2 buf[2][NN];
    const int row = blockIdx.x;
    const int t = threadIdx.x;
    #pragma unroll
    for (int u = 0; u < NN / BT; ++u) {
        int i = t + u * BT;
        buf[0][i] = make_float2(i == row ? 1.0f : 0.0f, 0.0f);
    }
    int cur = 0;
    __syncthreads();

    for (int d = 0; d < depth; ++d) {
        const float p0 = 1.0f / (1.0f + expf(-perm_logit[d * 3 + 0]));
        const float p1 = 1.0f / (1.0f + expf(-perm_logit[d * 3 + 1]));
        const float p2 = 1.0f / (1.0f + expf(-perm_logit[d * 3 + 2]));
        for (int m = 4; m <= NN; m <<= 1) {
            const int half = m >> 1;
            const int nxt = cur ^ 1;
            #pragma unroll
            for (int u = 0; u < NN / BT; ++u) {
                int i = t + u * BT;
                int blk = i & ~(m - 1);
                int j = i - blk;
                bool second = (j >= half);
                float pr = second ? p2 : p1;
                int sj  = second ? (2 * (j - half) + 1) : (2 * j);
                int rj  = second ? (m + half - 1 - j)   : (half - 1 - j);
                int srj = second ? (2 * (rj - half) + 1) : (2 * rj);
                float2 a  = buf[cur][blk + j];
                float2 bb = buf[cur][blk + sj];
                float2 c  = buf[cur][blk + rj];
                float2 dd = buf[cur][blk + srj];
                float ex = a.x + p0 * (bb.x - a.x);
                float ey = a.y + p0 * (bb.y - a.y);
                float fx = c.x + p0 * (dd.x - c.x);
                float fy = c.y + p0 * (dd.y - c.y);
                buf[nxt][i] = make_float2(ex + pr * (fx - ex), ey + pr * (fy - ey));
            }
            __syncthreads();
            cur = nxt;
        }
        const float2* abd = (const float2*)(abcd) + (size_t)d * (4 * NN - 4);
        int lh = 0;
        for (int m = 2; m <= NN; m <<= 1, ++lh) {
            const int half = m >> 1;
            const float2* W = abd + (4 * NN - 4 * m);
            const int nxt = cur ^ 1;
            #pragma unroll
            for (int u = 0; u < (NN / 2) / BT; ++u) {
                int p  = t + u * BT;
                int bi = p >> lh;
                int k  = p & (half - 1);
                int i0 = bi * m + k;
                int i1 = i0 + half;
                float2 x0 = buf[cur][i0];
                float2 x1 = buf[cur][i1];
                float2 A  = W[k];
                float2 Bw = W[half + k];
                float2 C  = W[2 * half + k];
                float2 D  = W[3 * half + k];
                float2 y0, y1;
                y0.x = A.x * x0.x - A.y * x0.y + Bw.x * x1.x - Bw.y * x1.y;
                y0.y = A.x * x0.y + A.y * x0.x + Bw.x * x1.y + Bw.y * x1.x;
                y1.x = C.x * x0.x - C.y * x0.y + D.x * x1.x - D.y * x1.y;
                y1.y = C.x * x0.y + C.y * x0.x + D.x * x1.y + D.y * x1.x;
                buf[nxt][i0] = y0;
                buf[nxt][i1] = y1;
            }
            __syncthreads();
            cur = nxt;
        }
    }
    #pragma unroll
    for (int u = 0; u < NN / BT; ++u) {
        int i = t + u * BT;
        g_W[(size_t)row * NN + i] = buf[cur][i].x;
    }
}

// ================= convert W -> transposed fp16 =================
__global__ void convW_kernel()
{
    __shared__ float tile[32][33];
    int tx = threadIdx.x, ty = threadIdx.y;
    int bx = blockIdx.x, by = blockIdx.y;
    #pragma unroll
    for (int k = 0; k < 4; ++k) {
        int krow = by * 32 + ty + 8 * k;
        tile[ty + 8 * k][tx] = g_W[(size_t)krow * NN + bx * 32 + tx];
    }
    __syncthreads();
    #pragma unroll
    for (int k = 0; k < 4; ++k) {
        int n  = bx * 32 + ty + 8 * k;
        int kk = by * 32 + tx;
        g_WhT[(size_t)n * NN + kk] = __float2half(tile[tx][ty + 8 * k]);
    }
}

// ================= convert x -> fp16 =================
__global__ void convX_kernel(const float* __restrict__ x, int n4)
{
    int i = blockIdx.x * blockDim.x + threadIdx.x;
    if (i >= n4) return;
    float4 v = ((const float4*)x)[i];
    __half2* dh = (__half2*)g_xh + i * 2;
    dh[0] = __half2(__float2half(v.x), __float2half(v.y));
    dh[1] = __half2(__float2half(v.z), __float2half(v.w));
}

// ================= HMMA GEMM: out = xh*Wh + bias (single pass) =================
// CTA tile 128x128, K-stage 32. 3-stage cp.async ring in dynamic smem, one
// __syncthreads per stage; next-stage issue after the barrier, before the MMAs.
// Smem rows padded to 40 halves (80B) -> conflict-free ldmatrix. 2 CTAs/SM.
#define TM 128
#define TN 128
#define TK 32
#define PAD 40
#define AST (TM * PAD)                  // half elems per A stage (5120)
#define BST (TN * PAD)
#define NRING 3
#define ABYTES (AST * 2)                // 10240 B
#define BBYTES (BST * 2)
#define SMEM_GEMM (NRING * (ABYTES + BBYTES))   // 61440 B
#define NSTAGES_TOT (NN / TK)           // 32

__global__ __launch_bounds__(256) void gemm_kernel(
    const float* __restrict__ bias, float* __restrict__ out)
{
    extern __shared__ __half smem[];
    __half* As = smem;                       // NRING stages of A
    __half* Bs = smem + NRING * AST;         // NRING stages of B

    const int tid = threadIdx.x;
    const int lane = tid & 31;
    const int wid = tid >> 5;
    const int wm = wid & 3;       // 4 warps over M (32 rows each)
    const int wn = wid >> 2;      // 2 warps over N (64 cols each)
    const int gn = blockIdx.x;    // N block (fast) -> A reuse in L2
    const int gm = blockIdx.y;    // M block

    float acc[2][8][4];
    #pragma unroll
    for (int mf = 0; mf < 2; ++mf)
        #pragma unroll
        for (int nf = 0; nf < 8; ++nf)
            #pragma unroll
            for (int q = 0; q < 4; ++q) acc[mf][nf][q] = 0.0f;

    const uint32_t sAbase = smem_u32(As);
    const uint32_t sBbase = smem_u32(Bs);

    // cp.async mapping: 512 16B-chunks per tile; thread t handles chunks t and t+256.
    const int r0  = tid >> 2;           // row 0..63
    const int cc0 = tid & 3;            // 16B chunk within 64B row window
    const uint32_t w0 = (uint32_t)(r0 * 80 + cc0 * 16);
    const uint32_t w1 = w0 + 64 * 80;

    auto issue = [&](int s, int slot) {
        const int k0 = s * TK;
        const __half* Ap = g_xh + (size_t)(gm * TM) * NN + k0;
        const __half* Bp = g_WhT + (size_t)(gn * TN) * NN + k0;
        const uint32_t sa = sAbase + (uint32_t)(slot * ABYTES);
        const uint32_t sb = sBbase + (uint32_t)(slot * BBYTES);
        CP_ASYNC16(sa + w0, Ap + (size_t)r0 * NN + cc0 * 8);
        CP_ASYNC16(sa + w1, Ap + (size_t)(r0 + 64) * NN + cc0 * 8);
        CP_ASYNC16(sb + w0, Bp + (size_t)r0 * NN + cc0 * 8);
        CP_ASYNC16(sb + w1, Bp + (size_t)(r0 + 64) * NN + cc0 * 8);
        CP_COMMIT();
    };

    // ldmatrix lane address components
    const int a_r = (lane & 7) | (((lane >> 3) & 1) << 3);   // row 0..15 within frag
    const int a_c = ((lane >> 4) & 1) * 8;                   // +8 elems for mats 2,3
    const int b_n = (lane & 7) | (((lane >> 4) & 1) << 3);   // n row within 16
    const int b_k = ((lane >> 3) & 1) * 8;                   // +8 elems for mats 1,3
    const uint32_t aoff = (uint32_t)((wm * 32 + a_r) * 80 + a_c * 2);
    const uint32_t boff = (uint32_t)((wn * 64 + b_n) * 80 + b_k * 2);

    // prologue: 2 stages in flight
    issue(0, 0);
    issue(1, 1);

    int slot = 0, islot = 2;   // compute slot; next issue slot
    for (int s = 0; s < NSTAGES_TOT; ++s) {
        if (s == NSTAGES_TOT - 1) { CP_WAIT0(); }
        else                      { CP_WAIT1(); }
        __syncthreads();   // stage s visible; all warps done with previous use of slot
        if (s + 2 < NSTAGES_TOT) {
            issue(s + 2, islot);
            if (++islot == NRING) islot = 0;
        }
        const uint32_t sa = sAbase + (uint32_t)(slot * ABYTES) + aoff;
        const uint32_t sb = sBbase + (uint32_t)(slot * BBYTES) + boff;
        if (++slot == NRING) slot = 0;
        #pragma unroll
        for (int kk = 0; kk < 2; ++kk) {
            uint32_t af[2][4];
            LDSM4(af[0], sa + kk * 32);
            LDSM4(af[1], sa + kk * 32 + 16 * 80);
            uint32_t bfr[4][4];
            #pragma unroll
            for (int g2 = 0; g2 < 4; ++g2)
                LDSM4(bfr[g2], sb + kk * 32 + g2 * 16 * 80);
            #pragma unroll
            for (int mf = 0; mf < 2; ++mf)
                #pragma unroll
                for (int nf = 0; nf < 8; ++nf) {
                    uint32_t bb[2] = { bfr[nf >> 1][(nf & 1) * 2],
                                       bfr[nf >> 1][(nf & 1) * 2 + 1] };
                    MMA16816(acc[mf][nf], af[mf], bb);
                }
        }
    }

    // epilogue: add bias, store fp32
    const int row0 = gm * TM + wm * 32 + (lane >> 2);
    const int col0 = gn * TN + wn * 64 + (lane & 3) * 2;
    #pragma unroll
    for (int mf = 0; mf < 2; ++mf) {
        #pragma unroll
        for (int nf = 0; nf < 8; ++nf) {
            const int r = row0 + mf * 16;
            const int c = col0 + nf * 8;
            const float b0 = __ldg(bias + c);
            const float b1 = __ldg(bias + c + 1);
            float2 v0 = make_float2(acc[mf][nf][0] + b0, acc[mf][nf][1] + b1);
            float2 v1 = make_float2(acc[mf][nf][2] + b0, acc[mf][nf][3] + b1);
            *(float2*)(out + (size_t)r * NN + c) = v0;
            *(float2*)(out + (size_t)(r + 8) * NN + c) = v1;
        }
    }
}

// ================= launch =================
extern "C" void kernel_launch(void* const* d_in, const int* in_sizes, int n_in,
                              void* d_out, int out_size)
{
    const float* x          = (const float*)d_in[0];  // (B, 1024)
    const float* perm_logit = (const float*)d_in[1];  // (DEPTH, 3)
    const float* abcd       = (const float*)d_in[2];  // (DEPTH, 4092, 2)
    const float* bias       = (const float*)d_in[3];  // (1024,)
    float* out = (float*)d_out;

    int Bn = in_sizes[0] / NN;
    int depth = in_sizes[1] / 3;

    static bool attr_set = false;
    if (!attr_set) {
        cudaFuncSetAttribute(gemm_kernel, cudaFuncAttributeMaxDynamicSharedMemorySize, SMEM_GEMM);
        attr_set = true;
    }

    // 1) M from butterfly on identity
    butterfly_ident_kernel<<<NN, BT>>>(perm_logit, abcd, depth);
    // 2) W -> transposed fp16
    convW_kernel<<<dim3(32, 32), dim3(32, 8)>>>();
    // 3) x -> fp16
    int n4 = Bn * NN / 4;
    convX_kernel<<<(n4 + 255) / 256, 256>>>(x, n4);
    // 4) HMMA GEMM, single pass, CTA 128x128, warp 32x64, 2 CTAs/SM
    gemm_kernel<<<dim3(NN / TN, Bn / TM), 256, SMEM_GEMM>>>(bias, out);
}

// round 13
// speedup vs baseline: 1.8474x; 1.0216x over previous
#include <cuda_runtime.h>
#include <cuda_fp16.h>
#include <math.h>
#include <stdint.h>

#define NN 1024
#define BT 256  // threads for butterfly kernel

// ---------------- scratch (__device__ globals; no runtime alloc) ----------------
__device__ __half  g_Wh[NN * NN];           // 2 MB : fp16(M), [k][n]  (row k = butterfly(e_k))
__device__ __half  g_xh[16384 * NN];        // 32 MB : fp16(x)

// ---------------- PTX helpers (all family-agnostic: sm_80+ features) ----------------
__device__ __forceinline__ uint32_t smem_u32(const void* p) {
    uint32_t a;
    asm("{ .reg .u64 t; cvta.to.shared.u64 t, %1; cvt.u32.u64 %0, t; }" : "=r"(a) : "l"(p));
    return a;
}
#define CP_ASYNC16(s, g) \
    asm volatile("cp.async.cg.shared.global [%0], [%1], 16;" :: "r"(s), "l"(g))
#define CP_COMMIT() asm volatile("cp.async.commit_group;" ::: "memory")
#define CP_WAIT1()  asm volatile("cp.async.wait_group 1;" ::: "memory")
#define CP_WAIT0()  asm volatile("cp.async.wait_group 0;" ::: "memory")
#define LDSM4(r, addr) \
    asm volatile("ldmatrix.sync.aligned.m8n8.x4.shared.b16 {%0,%1,%2,%3}, [%4];" \
        : "=r"((r)[0]), "=r"((r)[1]), "=r"((r)[2]), "=r"((r)[3]) : "r"(addr))
#define LDSM4T(r, addr) \
    asm volatile("ldmatrix.sync.aligned.m8n8.x4.trans.shared.b16 {%0,%1,%2,%3}, [%4];" \
        : "=r"((r)[0]), "=r"((r)[1]), "=r"((r)[2]), "=r"((r)[3]) : "r"(addr))
#define MMA16816(d, a, b) \
    asm volatile("mma.sync.aligned.m16n8k16.row.col.f32.f16.f16.f32 " \
        "{%0,%1,%2,%3}, {%4,%5,%6,%7}, {%8,%9}, {%0,%1,%2,%3};" \
        : "+f"((d)[0]), "+f"((d)[1]), "+f"((d)[2]), "+f"((d)[3]) \
        : "r"((a)[0]), "r"((a)[1]), "r"((a)[2]), "r"((a)[3]), "r"((b)[0]), "r"((b)[1]))

// ================= butterfly on identity rows -> g_Wh (fp16, [k][n]) =================
__global__ __launch_bounds__(BT) void butterfly_ident_kernel(
    const float* __restrict__ perm_logit, const float* __restrict__ abcd, int depth)
{
    __shared__ float2 buf[2][NN];
    const int row = blockIdx.x;
    const int t = threadIdx.x;
    #pragma unroll
    for (int u = 0; u < NN / BT; ++u) {
        int i = t + u * BT;
        buf[0][i] = make_float2(i == row ? 1.0f : 0.0f, 0.0f);
    }
    int cur = 0;
    __syncthreads();

    for (int d = 0; d < depth; ++d) {
        const float p0 = 1.0f / (1.0f + expf(-perm_logit[d * 3 + 0]));
        const float p1 = 1.0f / (1.0f + expf(-perm_logit[d * 3 + 1]));
        const float p2 = 1.0f / (1.0f + expf(-perm_logit[d * 3 + 2]));
        for (int m = 4; m <= NN; m <<= 1) {
            const int half = m >> 1;
            const int nxt = cur ^ 1;
            #pragma unroll
            for (int u = 0; u < NN / BT; ++u) {
                int i = t + u * BT;
                int blk = i & ~(m - 1);
                int j = i - blk;
                bool second = (j >= half);
                float pr = second ? p2 : p1;
                int sj  = second ? (2 * (j - half) + 1) : (2 * j);
                int rj  = second ? (m + half - 1 - j)   : (half - 1 - j);
                int srj = second ? (2 * (rj - half) + 1) : (2 * rj);
                float2 a  = buf[cur][blk + j];
                float2 bb = buf[cur][blk + sj];
                float2 c  = buf[cur][blk + rj];
                float2 dd = buf[cur][blk + srj];
                float ex = a.x + p0 * (bb.x - a.x);
                float ey = a.y + p0 * (bb.y - a.y);
                float fx = c.x + p0 * (dd.x - c.x);
                float fy = c.y + p0 * (dd.y - c.y);
                buf[nxt][i] = make_float2(ex + pr * (fx - ex), ey + pr * (fy - ey));
            }
            __syncthreads();
            cur = nxt;
        }
        const float2* abd = (const float2*)(abcd) + (size_t)d * (4 * NN - 4);
        int lh = 0;
        for (int m = 2; m <= NN; m <<= 1, ++lh) {
            const int half = m >> 1;
            const float2* W = abd + (4 * NN - 4 * m);
            const int nxt = cur ^ 1;
            #pragma unroll
            for (int u = 0; u < (NN / 2) / BT; ++u) {
                int p  = t + u * BT;
                int bi = p >> lh;
                int k  = p & (half - 1);
                int i0 = bi * m + k;
                int i1 = i0 + half;
                float2 x0 = buf[cur][i0];
                float2 x1 = buf[cur][i1];
                float2 A  = W[k];
                float2 Bw = W[half + k];
                float2 C  = W[2 * half + k];
                float2 D  = W[3 * half + k];
                float2 y0, y1;
                y0.x = A.x * x0.x - A.y * x0.y + Bw.x * x1.x - Bw.y * x1.y;
                y0.y = A.x * x0.y + A.y * x0.x + Bw.x * x1.y + Bw.y * x1.x;
                y1.x = C.x * x0.x - C.y * x0.y + D.x * x1.x - D.y * x1.y;
                y1.y = C.x * x0.y + C.y * x0.x + D.x * x1.y + D.y * x1.x;
                buf[nxt][i0] = y0;
                buf[nxt][i1] = y1;
            }
            __syncthreads();
            cur = nxt;
        }
    }
    // write fp16 directly, [k][n] layout (coalesced)
    #pragma unroll
    for (int u = 0; u < NN / BT; ++u) {
        int i = t + u * BT;
        g_Wh[(size_t)row * NN + i] = __float2half(buf[cur][i].x);
    }
}

// ================= convert x -> fp16 =================
__global__ void convX_kernel(const float* __restrict__ x, int n4)
{
    int i = blockIdx.x * blockDim.x + threadIdx.x;
    if (i >= n4) return;
    float4 v = ((const float4*)x)[i];
    __half2* dh = (__half2*)g_xh + i * 2;
    dh[0] = __half2(__float2half(v.x), __float2half(v.y));
    dh[1] = __half2(__float2half(v.z), __float2half(v.w));
}

// ================= HMMA GEMM: out = xh*Wh + bias (single pass) =================
// CTA tile 128x128, K-stage 32. 3-stage cp.async ring, one __syncthreads/stage.
// A smem: [m][k], 40-half (80B) stride, non-trans ldmatrix.
// B smem: [k][n], 136-half (272B) stride, TRANS ldmatrix (W stored un-transposed).
#define TM 128
#define TN 128
#define TK 32
#define APADH 40                        // halves per A row
#define BPADH 136                       // halves per B row ([k][n], 128 n + pad)
#define AST (TM * APADH)                // 5120 halves
#define BSTG (TK * BPADH)               // 4352 halves
#define NRING 3
#define ABYTES (AST * 2)                // 10240 B
#define BBYTES (BSTG * 2)               // 8704 B
#define SMEM_GEMM (NRING * (ABYTES + BBYTES))   // 56832 B
#define NSTAGES_TOT (NN / TK)           // 32

__global__ __launch_bounds__(256) void gemm_kernel(
    const float* __restrict__ bias, float* __restrict__ out)
{
    extern __shared__ __half smem[];
    __half* As = smem;                       // NRING stages of A
    __half* Bs = smem + NRING * AST;         // NRING stages of B

    const int tid = threadIdx.x;
    const int lane = tid & 31;
    const int wid = tid >> 5;
    const int wm = wid & 3;       // 4 warps over M (32 rows each)
    const int wn = wid >> 2;      // 2 warps over N (64 cols each)
    const int gn = blockIdx.x;    // N block (fast) -> A reuse in L2
    const int gm = blockIdx.y;    // M block

    float acc[2][8][4];
    #pragma unroll
    for (int mf = 0; mf < 2; ++mf)
        #pragma unroll
        for (int nf = 0; nf < 8; ++nf)
            #pragma unroll
            for (int q = 0; q < 4; ++q) acc[mf][nf][q] = 0.0f;

    const uint32_t sAbase = smem_u32(As);
    const uint32_t sBbase = smem_u32(Bs);

    // A cp.async: 128 rows x 64B = 512 chunks; thread t: rows t>>2 and (t>>2)+64.
    const int ar0  = tid >> 2;
    const int acc0 = tid & 3;
    const uint32_t wa0 = (uint32_t)(ar0 * (APADH * 2) + acc0 * 16);
    const uint32_t wa1 = wa0 + 64 * (APADH * 2);
    // B cp.async: 32 k-rows x 256B = 512 chunks; thread t: row t>>3, chunks (t&7), (t&7)+8.
    const int br0 = tid >> 3;
    const int bc0 = tid & 7;
    const uint32_t wb0 = (uint32_t)(br0 * (BPADH * 2) + bc0 * 16);
    const uint32_t wb1 = wb0 + 128;          // chunk +8 -> +64 halves

    auto issue = [&](int s, int slot) {
        const int k0 = s * TK;
        const __half* Ap = g_xh + (size_t)(gm * TM) * NN + k0;
        const __half* Bp = g_Wh + (size_t)k0 * NN + gn * TN;
        const uint32_t sa = sAbase + (uint32_t)(slot * ABYTES);
        const uint32_t sb = sBbase + (uint32_t)(slot * BBYTES);
        CP_ASYNC16(sa + wa0, Ap + (size_t)ar0 * NN + acc0 * 8);
        CP_ASYNC16(sa + wa1, Ap + (size_t)(ar0 + 64) * NN + acc0 * 8);
        CP_ASYNC16(sb + wb0, Bp + (size_t)br0 * NN + bc0 * 8);
        CP_ASYNC16(sb + wb1, Bp + (size_t)br0 * NN + bc0 * 8 + 64);
        CP_COMMIT();
    };

    // A ldmatrix lane addressing (non-trans, [m][k])
    const int a_r = (lane & 7) | (((lane >> 3) & 1) << 3);   // m-row 0..15 within frag
    const int a_c = ((lane >> 4) & 1) * 8;                   // +8 k for mats 2,3
    const uint32_t aoff = (uint32_t)((wm * 32 + a_r) * (APADH * 2) + a_c * 2);
    // B ldmatrix lane addressing (TRANS, [k][n]): lanes supply k-rows.
    // mats: 0=(k0-7,n0-7) 1=(k8-15,n0-7) 2=(k0-7,n8-15) 3=(k8-15,n8-15)
    const int bk_r = (lane & 7) | (((lane >> 3) & 1) << 3);  // k-row 0..15 within frag
    const int bn_c = ((lane >> 4) & 1) * 8;                  // +8 n for mats 2,3
    const uint32_t boff = (uint32_t)(bk_r * (BPADH * 2) + (wn * 64 + bn_c) * 2);

    // prologue: 2 stages in flight
    issue(0, 0);
    issue(1, 1);

    int slot = 0, islot = 2;   // compute slot; next issue slot
    for (int s = 0; s < NSTAGES_TOT; ++s) {
        if (s == NSTAGES_TOT - 1) { CP_WAIT0(); }
        else                      { CP_WAIT1(); }
        __syncthreads();   // stage s visible; all warps done with previous use of slot
        if (s + 2 < NSTAGES_TOT) {
            issue(s + 2, islot);
            if (++islot == NRING) islot = 0;
        }
        const uint32_t sa = sAbase + (uint32_t)(slot * ABYTES) + aoff;
        const uint32_t sb = sBbase + (uint32_t)(slot * BBYTES) + boff;
        if (++slot == NRING) slot = 0;
        #pragma unroll
        for (int kk = 0; kk < 2; ++kk) {
            uint32_t af[2][4];
            LDSM4(af[0], sa + kk * 32);
            LDSM4(af[1], sa + kk * 32 + 16 * (APADH * 2));
            uint32_t bfr[4][4];
            #pragma unroll
            for (int g2 = 0; g2 < 4; ++g2)
                LDSM4T(bfr[g2], sb + kk * 16 * (BPADH * 2) + g2 * 16 * 2);
            #pragma unroll
            for (int mf = 0; mf < 2; ++mf)
                #pragma unroll
                for (int nf = 0; nf < 8; ++nf) {
                    uint32_t bb[2] = { bfr[nf >> 1][(nf & 1) * 2],
                                       bfr[nf >> 1][(nf & 1) * 2 + 1] };
                    MMA16816(acc[mf][nf], af[mf], bb);
                }
        }
    }

    // epilogue: add bias, store fp32
    const int row0 = gm * TM + wm * 32 + (lane >> 2);
    const int col0 = gn * TN + wn * 64 + (lane & 3) * 2;
    #pragma unroll
    for (int mf = 0; mf < 2; ++mf) {
        #pragma unroll
        for (int nf = 0; nf < 8; ++nf) {
            const int r = row0 + mf * 16;
            const int c = col0 + nf * 8;
            const float b0 = __ldg(bias + c);
            const float b1 = __ldg(bias + c + 1);
            float2 v0 = make_float2(acc[mf][nf][0] + b0, acc[mf][nf][1] + b1);
            float2 v1 = make_float2(acc[mf][nf][2] + b0, acc[mf][nf][3] + b1);
            *(float2*)(out + (size_t)r * NN + c) = v0;
            *(float2*)(out + (size_t)(r + 8) * NN + c) = v1;
        }
    }
}

// ================= launch =================
extern "C" void kernel_launch(void* const* d_in, const int* in_sizes, int n_in,
                              void* d_out, int out_size)
{
    const float* x          = (const float*)d_in[0];  // (B, 1024)
    const float* perm_logit = (const float*)d_in[1];  // (DEPTH, 3)
    const float* abcd       = (const float*)d_in[2];  // (DEPTH, 4092, 2)
    const float* bias       = (const float*)d_in[3];  // (1024,)
    float* out = (float*)d_out;

    int Bn = in_sizes[0] / NN;
    int depth = in_sizes[1] / 3;

    static bool attr_set = false;
    if (!attr_set) {
        cudaFuncSetAttribute(gemm_kernel, cudaFuncAttributeMaxDynamicSharedMemorySize, SMEM_GEMM);
        attr_set = true;
    }

    // 1) M from butterfly on identity -> fp16 [k][n] directly
    butterfly_ident_kernel<<<NN, BT>>>(perm_logit, abcd, depth);
    // 2) x -> fp16
    int n4 = Bn * NN / 4;
    convX_kernel<<<(n4 + 255) / 256, 256>>>(x, n4);
    // 3) HMMA GEMM, single pass, CTA 128x128, warp 32x64, trans-B
    gemm_kernel<<<dim3(NN / TN, Bn / TM), 256, SMEM_GEMM>>>(bias, out);
}

// round 16
// speedup vs baseline: 1.9299x; 1.0447x over previous
#include <cuda_runtime.h>
#include <cuda_fp16.h>
#include <math.h>
#include <stdint.h>

#define NN 1024
#define BT 256  // threads for butterfly kernel

// ---------------- scratch (__device__ globals; no runtime alloc) ----------------
__device__ __half  g_Wh[NN * NN];           // 2 MB : fp16(M), [k][n]  (row k = butterfly(e_k))
__device__ __half  g_xh[16384 * NN];        // 32 MB : fp16(x)

// ---------------- PTX helpers (all family-agnostic: sm_80+ features) ----------------
__device__ __forceinline__ uint32_t smem_u32(const void* p) {
    uint32_t a;
    asm("{ .reg .u64 t; cvta.to.shared.u64 t, %1; cvt.u32.u64 %0, t; }" : "=r"(a) : "l"(p));
    return a;
}
#define CP_ASYNC16(s, g) \
    asm volatile("cp.async.cg.shared.global [%0], [%1], 16;" :: "r"(s), "l"(g))
#define CP_COMMIT() asm volatile("cp.async.commit_group;" ::: "memory")
#define CP_WAIT1()  asm volatile("cp.async.wait_group 1;" ::: "memory")
#define CP_WAIT0()  asm volatile("cp.async.wait_group 0;" ::: "memory")
#define LDSM4(r, addr) \
    asm volatile("ldmatrix.sync.aligned.m8n8.x4.shared.b16 {%0,%1,%2,%3}, [%4];" \
        : "=r"((r)[0]), "=r"((r)[1]), "=r"((r)[2]), "=r"((r)[3]) : "r"(addr))
#define LDSM4T(r, addr) \
    asm volatile("ldmatrix.sync.aligned.m8n8.x4.trans.shared.b16 {%0,%1,%2,%3}, [%4];" \
        : "=r"((r)[0]), "=r"((r)[1]), "=r"((r)[2]), "=r"((r)[3]) : "r"(addr))
#define MMA16816(d, a, b) \
    asm volatile("mma.sync.aligned.m16n8k16.row.col.f32.f16.f16.f32 " \
        "{%0,%1,%2,%3}, {%4,%5,%6,%7}, {%8,%9}, {%0,%1,%2,%3};" \
        : "+f"((d)[0]), "+f"((d)[1]), "+f"((d)[2]), "+f"((d)[3]) \
        : "r"((a)[0]), "r"((a)[1]), "r"((a)[2]), "r"((a)[3]), "r"((b)[0]), "r"((b)[1]))

// ================= butterfly on identity rows -> g_Wh (fp16, [k][n]) =================
// Depth-0 PERM chain only: one-hot support stays within the size-m block
// containing `row` (blocks grow with m, so ping-pong staleness is always
// overwritten; elsewhere both buffers are zero). Diag chain restarts at m=2
// AFTER the full-width m=1024 perm mix, so it must run dense.
__global__ __launch_bounds__(BT) void butterfly_ident_kernel(
    const float* __restrict__ perm_logit, const float* __restrict__ abcd, int depth)
{
    __shared__ float2 buf[2][NN];
    const int row = blockIdx.x;
    const int t = threadIdx.x;
    // zero-init BOTH buffers (sparse perm phase relies on zeros outside blocks)
    #pragma unroll
    for (int u = 0; u < NN / BT; ++u) {
        int i = t + u * BT;
        buf[0][i] = make_float2(i == row ? 1.0f : 0.0f, 0.0f);
        buf[1][i] = make_float2(0.0f, 0.0f);
    }
    int cur = 0;
    __syncthreads();

    for (int d = 0; d < depth; ++d) {
        const float p0 = 1.0f / (1.0f + expf(-perm_logit[d * 3 + 0]));
        const float p1 = 1.0f / (1.0f + expf(-perm_logit[d * 3 + 1]));
        const float p2 = 1.0f / (1.0f + expf(-perm_logit[d * 3 + 2]));

        // ---- perm factors, m = 4..1024 (sparse for d==0) ----
        for (int m = 4; m <= NN; m <<= 1) {
            const int half = m >> 1;
            const int nxt = cur ^ 1;
            const int base = (d == 0) ? (row & ~(m - 1)) : 0;
            const int lim  = (d == 0) ? m : NN;
            for (int idx = t; idx < lim; idx += BT) {
                int i = base + idx;
                int blk = i & ~(m - 1);
                int j = i - blk;
                bool second = (j >= half);
                float pr = second ? p2 : p1;
                int sj  = second ? (2 * (j - half) + 1) : (2 * j);
                int rj  = second ? (m + half - 1 - j)   : (half - 1 - j);
                int srj = second ? (2 * (rj - half) + 1) : (2 * rj);
                float2 a  = buf[cur][blk + j];
                float2 bb = buf[cur][blk + sj];
                float2 c  = buf[cur][blk + rj];
                float2 dd = buf[cur][blk + srj];
                float ex = a.x + p0 * (bb.x - a.x);
                float ey = a.y + p0 * (bb.y - a.y);
                float fx = c.x + p0 * (dd.x - c.x);
                float fy = c.y + p0 * (dd.y - c.y);
                buf[nxt][i] = make_float2(ex + pr * (fx - ex), ey + pr * (fy - ey));
            }
            __syncthreads();
            cur = nxt;
        }

        // ---- diag factors, m = 2..1024 (ALWAYS dense: support is full-width) ----
        const float2* abd = (const float2*)(abcd) + (size_t)d * (4 * NN - 4);
        int lh = 0;
        for (int m = 2; m <= NN; m <<= 1, ++lh) {
            const int half = m >> 1;
            const float2* W = abd + (4 * NN - 4 * m);
            const int nxt = cur ^ 1;
            #pragma unroll
            for (int u = 0; u < (NN / 2) / BT; ++u) {
                int p  = t + u * BT;
                int bi = p >> lh;
                int k  = p & (half - 1);
                int i0 = bi * m + k;
                int i1 = i0 + half;
                float2 x0 = buf[cur][i0];
                float2 x1 = buf[cur][i1];
                float2 A  = W[k];
                float2 Bw = W[half + k];
                float2 C  = W[2 * half + k];
                float2 D  = W[3 * half + k];
                float2 y0, y1;
                y0.x = A.x * x0.x - A.y * x0.y + Bw.x * x1.x - Bw.y * x1.y;
                y0.y = A.x * x0.y + A.y * x0.x + Bw.x * x1.y + Bw.y * x1.x;
                y1.x = C.x * x0.x - C.y * x0.y + D.x * x1.x - D.y * x1.y;
                y1.y = C.x * x0.y + C.y * x0.x + D.x * x1.y + D.y * x1.x;
                buf[nxt][i0] = y0;
                buf[nxt][i1] = y1;
            }
            __syncthreads();
            cur = nxt;
        }
    }
    // write fp16 directly, [k][n] layout (coalesced)
    #pragma unroll
    for (int u = 0; u < NN / BT; ++u) {
        int i = t + u * BT;
        g_Wh[(size_t)row * NN + i] = __float2half(buf[cur][i].x);
    }
}

// ================= convert x -> fp16 =================
__global__ void convX_kernel(const float* __restrict__ x, int n4)
{
    int i = blockIdx.x * blockDim.x + threadIdx.x;
    if (i >= n4) return;
    float4 v = ((const float4*)x)[i];
    __half2* dh = (__half2*)g_xh + i * 2;
    dh[0] = __half2(__float2half(v.x), __float2half(v.y));
    dh[1] = __half2(__float2half(v.z), __float2half(v.w));
}

// ================= HMMA GEMM: out = xh*Wh + bias (single pass) =================
// CTA tile 128x128, K-stage 32. 3-stage cp.async ring, one __syncthreads/stage.
// A smem: [m][k], 40-half (80B) stride, non-trans ldmatrix.
// B smem: [k][n], 136-half (272B) stride, TRANS ldmatrix (W stored un-transposed).
#define TM 128
#define TN 128
#define TK 32
#define APADH 40                        // halves per A row
#define BPADH 136                       // halves per B row ([k][n], 128 n + pad)
#define AST (TM * APADH)                // 5120 halves
#define BSTG (TK * BPADH)               // 4352 halves
#define NRING 3
#define ABYTES (AST * 2)                // 10240 B
#define BBYTES (BSTG * 2)               // 8704 B
#define SMEM_GEMM (NRING * (ABYTES + BBYTES))   // 56832 B
#define NSTAGES_TOT (NN / TK)           // 32

__global__ __launch_bounds__(256) void gemm_kernel(
    const float* __restrict__ bias, float* __restrict__ out)
{
    extern __shared__ __half smem[];
    __half* As = smem;                       // NRING stages of A
    __half* Bs = smem + NRING * AST;         // NRING stages of B

    const int tid = threadIdx.x;
    const int lane = tid & 31;
    const int wid = tid >> 5;
    const int wm = wid & 3;       // 4 warps over M (32 rows each)
    const int wn = wid >> 2;      // 2 warps over N (64 cols each)
    const int gn = blockIdx.x;    // N block (fast) -> A reuse in L2
    const int gm = blockIdx.y;    // M block

    float acc[2][8][4];
    #pragma unroll
    for (int mf = 0; mf < 2; ++mf)
        #pragma unroll
        for (int nf = 0; nf < 8; ++nf)
            #pragma unroll
            for (int q = 0; q < 4; ++q) acc[mf][nf][q] = 0.0f;

    const uint32_t sAbase = smem_u32(As);
    const uint32_t sBbase = smem_u32(Bs);

    // A cp.async: 128 rows x 64B = 512 chunks; thread t: rows t>>2 and (t>>2)+64.
    const int ar0  = tid >> 2;
    const int acc0 = tid & 3;
    const uint32_t wa0 = (uint32_t)(ar0 * (APADH * 2) + acc0 * 16);
    const uint32_t wa1 = wa0 + 64 * (APADH * 2);
    // B cp.async: 32 k-rows x 256B = 512 chunks; thread t: row t>>3, chunks (t&7), (t&7)+8.
    const int br0 = tid >> 3;
    const int bc0 = tid & 7;
    const uint32_t wb0 = (uint32_t)(br0 * (BPADH * 2) + bc0 * 16);
    const uint32_t wb1 = wb0 + 128;          // chunk +8 -> +64 halves

    auto issue = [&](int s, int slot) {
        const int k0 = s * TK;
        const __half* Ap = g_xh + (size_t)(gm * TM) * NN + k0;
        const __half* Bp = g_Wh + (size_t)k0 * NN + gn * TN;
        const uint32_t sa = sAbase + (uint32_t)(slot * ABYTES);
        const uint32_t sb = sBbase + (uint32_t)(slot * BBYTES);
        CP_ASYNC16(sa + wa0, Ap + (size_t)ar0 * NN + acc0 * 8);
        CP_ASYNC16(sa + wa1, Ap + (size_t)(ar0 + 64) * NN + acc0 * 8);
        CP_ASYNC16(sb + wb0, Bp + (size_t)br0 * NN + bc0 * 8);
        CP_ASYNC16(sb + wb1, Bp + (size_t)br0 * NN + bc0 * 8 + 64);
        CP_COMMIT();
    };

    // A ldmatrix lane addressing (non-trans, [m][k])
    const int a_r = (lane & 7) | (((lane >> 3) & 1) << 3);   // m-row 0..15 within frag
    const int a_c = ((lane >> 4) & 1) * 8;                   // +8 k for mats 2,3
    const uint32_t aoff = (uint32_t)((wm * 32 + a_r) * (APADH * 2) + a_c * 2);
    // B ldmatrix lane addressing (TRANS, [k][n]): lanes supply k-rows.
    const int bk_r = (lane & 7) | (((lane >> 3) & 1) << 3);  // k-row 0..15 within frag
    const int bn_c = ((lane >> 4) & 1) * 8;                  // +8 n for mats 2,3
    const uint32_t boff = (uint32_t)(bk_r * (BPADH * 2) + (wn * 64 + bn_c) * 2);

    // prologue: 2 stages in flight
    issue(0, 0);
    issue(1, 1);

    int slot = 0, islot = 2;   // compute slot; next issue slot
    for (int s = 0; s < NSTAGES_TOT; ++s) {
        if (s == NSTAGES_TOT - 1) { CP_WAIT0(); }
        else                      { CP_WAIT1(); }
        __syncthreads();   // stage s visible; all warps done with previous use of slot
        if (s + 2 < NSTAGES_TOT) {
            issue(s + 2, islot);
            if (++islot == NRING) islot = 0;
        }
        const uint32_t sa = sAbase + (uint32_t)(slot * ABYTES) + aoff;
        const uint32_t sb = sBbase + (uint32_t)(slot * BBYTES) + boff;
        if (++slot == NRING) slot = 0;
        #pragma unroll
        for (int kk = 0; kk < 2; ++kk) {
            uint32_t af[2][4];
            LDSM4(af[0], sa + kk * 32);
            LDSM4(af[1], sa + kk * 32 + 16 * (APADH * 2));
            uint32_t bfr[4][4];
            #pragma unroll
            for (int g2 = 0; g2 < 4; ++g2)
                LDSM4T(bfr[g2], sb + kk * 16 * (BPADH * 2) + g2 * 16 * 2);
            #pragma unroll
            for (int mf = 0; mf < 2; ++mf)
                #pragma unroll
                for (int nf = 0; nf < 8; ++nf) {
                    uint32_t bb[2] = { bfr[nf >> 1][(nf & 1) * 2],
                                       bfr[nf >> 1][(nf & 1) * 2 + 1] };
                    MMA16816(acc[mf][nf], af[mf], bb);
                }
        }
    }

    // epilogue: add bias, store fp32
    const int row0 = gm * TM + wm * 32 + (lane >> 2);
    const int col0 = gn * TN + wn * 64 + (lane & 3) * 2;
    #pragma unroll
    for (int mf = 0; mf < 2; ++mf) {
        #pragma unroll
        for (int nf = 0; nf < 8; ++nf) {
            const int r = row0 + mf * 16;
            const int c = col0 + nf * 8;
            const float b0 = __ldg(bias + c);
            const float b1 = __ldg(bias + c + 1);
            float2 v0 = make_float2(acc[mf][nf][0] + b0, acc[mf][nf][1] + b1);
            float2 v1 = make_float2(acc[mf][nf][2] + b0, acc[mf][nf][3] + b1);
            *(float2*)(out + (size_t)r * NN + c) = v0;
            *(float2*)(out + (size_t)(r + 8) * NN + c) = v1;
        }
    }
}

// ================= launch =================
extern "C" void kernel_launch(void* const* d_in, const int* in_sizes, int n_in,
                              void* d_out, int out_size)
{
    const float* x          = (const float*)d_in[0];  // (B, 1024)
    const float* perm_logit = (const float*)d_in[1];  // (DEPTH, 3)
    const float* abcd       = (const float*)d_in[2];  // (DEPTH, 4092, 2)
    const float* bias       = (const float*)d_in[3];  // (1024,)
    float* out = (float*)d_out;

    int Bn = in_sizes[0] / NN;
    int depth = in_sizes[1] / 3;

    static bool attr_set = false;
    if (!attr_set) {
        cudaFuncSetAttribute(gemm_kernel, cudaFuncAttributeMaxDynamicSharedMemorySize, SMEM_GEMM);
        attr_set = true;
    }

    // 1) M from butterfly on identity -> fp16 [k][n] (depth-0 perm chain sparse)
    butterfly_ident_kernel<<<NN, BT>>>(perm_logit, abcd, depth);
    // 2) x -> fp16
    int n4 = Bn * NN / 4;
    convX_kernel<<<(n4 + 255) / 256, 256>>>(x, n4);
    // 3) HMMA GEMM, single pass, CTA 128x128, warp 32x64, trans-B
    gemm_kernel<<<dim3(NN / TN, Bn / TM), 256, SMEM_GEMM>>>(bias, out);
}